// round 2
// baseline (speedup 1.0000x reference)
#include <cuda_runtime.h>
#include <math.h>

// MaskedAutoregressiveFlow: fused 8-layer coupling flow.
// B=16384, F=64, CTX=128, HID=512, L=8, NB=2.
// One persistent-style fused kernel: 512 CTAs x 256 threads, 32 samples/CTA.
// All activations stay in SMEM; weights stream through L2.

namespace {
constexpr int B_TOT  = 16384;
constexpr int F_DIM  = 64;
constexpr int CTX_D  = 128;
constexpr int HID_D  = 512;
constexpr int N_LAY  = 8;
constexpr int N_T    = 32;          // F/2
constexpr int IN_DIM = 160;         // N_T + CTX
constexpr int TB     = 32;          // samples per CTA
constexpr int NTHR   = 256;
}

// Generic [TB x K] @ [K x 512] + bias -> relu -> outbuf (SMEM, row stride 512).
// Thread layout: tx in [0,32) covers neurons {128u + 4tx + j}, ty in [0,8) covers
// samples srow..srow+3. Reads of `in` are warp-broadcast LDS; W loads are
// coalesced LDG.128. Safe for in == outbuf (compute-all, barrier, write, barrier).
template<int K>
__device__ __forceinline__ void dense_relu_512(
    const float* __restrict__ in, const int instride,
    const float* __restrict__ W,       // row-major [K][512]
    const float* __restrict__ bias,    // [512]
    float* __restrict__ outbuf,        // [TB][512]
    const int tx, const int srow)
{
    float acc[4][16];
#pragma unroll
    for (int u = 0; u < 4; ++u) {
        float4 b4 = *((const float4*)bias + tx + 32 * u);
#pragma unroll
        for (int si = 0; si < 4; ++si) {
            acc[si][4*u+0] = b4.x; acc[si][4*u+1] = b4.y;
            acc[si][4*u+2] = b4.z; acc[si][4*u+3] = b4.w;
        }
    }

    for (int k = 0; k < K; k += 4) {
        float4 av[4];
#pragma unroll
        for (int si = 0; si < 4; ++si)
            av[si] = *(const float4*)&in[(srow + si) * instride + k];
#pragma unroll
        for (int kk = 0; kk < 4; ++kk) {
#pragma unroll
            for (int u = 0; u < 4; ++u) {
                float4 w = *((const float4*)&W[(k + kk) * HID_D] + tx + 32 * u);
#pragma unroll
                for (int si = 0; si < 4; ++si) {
                    const float a = reinterpret_cast<const float*>(&av[si])[kk];
                    acc[si][4*u+0] = fmaf(a, w.x, acc[si][4*u+0]);
                    acc[si][4*u+1] = fmaf(a, w.y, acc[si][4*u+1]);
                    acc[si][4*u+2] = fmaf(a, w.z, acc[si][4*u+2]);
                    acc[si][4*u+3] = fmaf(a, w.w, acc[si][4*u+3]);
                }
            }
        }
    }

    __syncthreads();   // everyone done reading `in` before we overwrite it
#pragma unroll
    for (int si = 0; si < 4; ++si) {
#pragma unroll
        for (int u = 0; u < 4; ++u) {
            float4 r;
            r.x = fmaxf(acc[si][4*u+0], 0.0f);
            r.y = fmaxf(acc[si][4*u+1], 0.0f);
            r.z = fmaxf(acc[si][4*u+2], 0.0f);
            r.w = fmaxf(acc[si][4*u+3], 0.0f);
            *(float4*)&outbuf[(srow + si) * HID_D + 4 * tx + 128 * u] = r;
        }
    }
    __syncthreads();
}

__global__ __launch_bounds__(NTHR, 2)
void maf_fused_kernel(
    const float* __restrict__ inputs,   // [B,64]
    const float* __restrict__ context,  // [B,128]
    const float* __restrict__ W_in,     // [L,160,512]
    const float* __restrict__ b_in,     // [L,512]
    const float* __restrict__ W_h,      // [L,2,512,512]
    const float* __restrict__ b_h,      // [L,2,512]
    const float* __restrict__ W_out,    // [L,512,64]
    const float* __restrict__ b_out,    // [L,64]
    const int*   __restrict__ perms,    // [L-1,64]
    float* __restrict__ out)            // [B*64] x, then [B] logdet
{
    extern __shared__ float smem[];
    float* act   = smem;                       // TB*HID   (h buffer)
    float* actA  = act  + TB * HID_D;          // TB*IN_DIM (GEMM1 input)
    float* xbuf0 = actA + TB * IN_DIM;         // TB*F
    float* xbuf1 = xbuf0 + TB * F_DIM;         // TB*F
    int*   pm    = (int*)(xbuf1 + TB * F_DIM); // 64

    const int tid  = threadIdx.x;
    const int tx   = tid & 31;
    const int ty   = tid >> 5;
    const int srow = ty * 4;
    const int base = blockIdx.x * TB;

    // x = clip(inputs, -1, 1)
    for (int idx = tid; idx < TB * F_DIM; idx += NTHR) {
        float v = inputs[base * F_DIM + idx];
        xbuf0[idx] = fminf(1.0f, fmaxf(-1.0f, v));
    }
    // context staged ONCE into actA[:, 32:160] (never changes across layers)
    for (int idx = tid; idx < TB * CTX_D; idx += NTHR) {
        int s = idx >> 7, c = idx & 127;
        actA[s * IN_DIM + N_T + c] = context[(base + s) * CTX_D + c];
    }

    float ldacc[4] = {0.0f, 0.0f, 0.0f, 0.0f};
    float* xc = xbuf0;
    float* xn = xbuf1;
    __syncthreads();

    for (int layer = 0; layer < N_LAY; ++layer) {
        const int idOff = (layer & 1) ? 0 : 1;   // id_idx  = 2j + idOff
        const int tOff  = (layer & 1) ? 1 : 0;   // t_idx   = 2j + tOff

        if (layer < N_LAY - 1 && tid < F_DIM)
            pm[tid] = perms[layer * F_DIM + tid];

        // id_split -> actA[:, 0:32]
        for (int idx = tid; idx < TB * N_T; idx += NTHR) {
            int s = idx >> 5, j = idx & 31;
            actA[s * IN_DIM + j] = xc[s * F_DIM + 2 * j + idOff];
        }
        __syncthreads();

        // h = relu(a @ W_in + b_in)
        dense_relu_512<IN_DIM>(actA, IN_DIM,
                               W_in + layer * IN_DIM * HID_D,
                               b_in + layer * HID_D,
                               act, tx, srow);
        // two hidden blocks
        dense_relu_512<HID_D>(act, HID_D,
                              W_h + (layer * 2 + 0) * HID_D * HID_D,
                              b_h + (layer * 2 + 0) * HID_D,
                              act, tx, srow);
        dense_relu_512<HID_D>(act, HID_D,
                              W_h + (layer * 2 + 1) * HID_D * HID_D,
                              b_h + (layer * 2 + 1) * HID_D,
                              act, tx, srow);

        // p = h @ W_out + b_out  (N=64: lane tx owns shift[tx] and prescale[tx])
        {
            const float* W    = W_out + layer * HID_D * F_DIM;
            const float* bias = b_out + layer * F_DIM;
            float p0[4], p1[4];
            const float bs0 = bias[tx];
            const float bs1 = bias[tx + 32];
#pragma unroll
            for (int si = 0; si < 4; ++si) { p0[si] = bs0; p1[si] = bs1; }

            for (int k = 0; k < HID_D; k += 4) {
                float4 av[4];
#pragma unroll
                for (int si = 0; si < 4; ++si)
                    av[si] = *(const float4*)&act[(srow + si) * HID_D + k];
#pragma unroll
                for (int kk = 0; kk < 4; ++kk) {
                    const float w0 = W[(k + kk) * F_DIM + tx];
                    const float w1 = W[(k + kk) * F_DIM + tx + 32];
#pragma unroll
                    for (int si = 0; si < 4; ++si) {
                        const float a = reinterpret_cast<const float*>(&av[si])[kk];
                        p0[si] = fmaf(a, w0, p0[si]);
                        p1[si] = fmaf(a, w1, p1[si]);
                    }
                }
            }

            // epilogue: scale/shift the transform half, accumulate logdet
#pragma unroll
            for (int si = 0; si < 4; ++si) {
                const float sc = 1.0f / (1.0f + expf(-(p1[si] + 2.0f))) + 0.001f;
                const float sh = p0[si];
                const int   s  = srow + si;
                const int   f  = 2 * tx + tOff;
                const float tr = xc[s * F_DIM + f];
                xc[s * F_DIM + f] = fmaf(tr, sc, sh);
                float ls = logf(sc);
#pragma unroll
                for (int off = 16; off > 0; off >>= 1)
                    ls += __shfl_xor_sync(0xffffffffu, ls, off);
                ldacc[si] += ls;
            }
        }

        __syncthreads();  // t-feature updates visible to all

        if (layer < N_LAY - 1) {
            // x = x[:, perm]
            for (int idx = tid; idx < TB * F_DIM; idx += NTHR) {
                int s = idx >> 6, f = idx & 63;
                xn[idx] = xc[s * F_DIM + pm[f]];
            }
            float* t = xc; xc = xn; xn = t;
            __syncthreads();
        }
    }

    // output: clip(x) then logdet
    for (int idx = tid; idx < TB * F_DIM; idx += NTHR)
        out[base * F_DIM + idx] = fminf(1.0f, fmaxf(-1.0f, xc[idx]));

    if (tx == 0) {
#pragma unroll
        for (int si = 0; si < 4; ++si)
            out[B_TOT * F_DIM + base + srow + si] = ldacc[si];
    }
}

extern "C" void kernel_launch(void* const* d_in, const int* in_sizes, int n_in,
                              void* d_out, int out_size)
{
    const float* inputs  = (const float*)d_in[0];
    const float* context = (const float*)d_in[1];
    const float* W_in    = (const float*)d_in[2];
    const float* b_in    = (const float*)d_in[3];
    const float* W_h     = (const float*)d_in[4];
    const float* b_h     = (const float*)d_in[5];
    const float* W_out   = (const float*)d_in[6];
    const float* b_out   = (const float*)d_in[7];
    const int*   perms   = (const int*)d_in[8];
    float* out = (float*)d_out;

    const int smem_bytes = (TB * HID_D + TB * IN_DIM + 2 * TB * F_DIM + 64) * (int)sizeof(float);
    cudaFuncSetAttribute(maf_fused_kernel,
                         cudaFuncAttributeMaxDynamicSharedMemorySize, smem_bytes);

    dim3 grid(B_TOT / TB);
    dim3 block(NTHR);
    maf_fused_kernel<<<grid, block, smem_bytes>>>(
        inputs, context, W_in, b_in, W_h, b_h, W_out, b_out, perms, out);
}

// round 3
// speedup vs baseline: 1.0002x; 1.0002x over previous
#include <cuda_runtime.h>
#include <math.h>

// MaskedAutoregressiveFlow: fused 8-layer coupling flow.
// B=16384, F=64, CTX=128, HID=512, L=8, NB=2.
// One persistent-style fused kernel: 512 CTAs x 256 threads, 32 samples/CTA.
// All activations stay in SMEM; weights stream through L2.

namespace {
constexpr int B_TOT  = 16384;
constexpr int F_DIM  = 64;
constexpr int CTX_D  = 128;
constexpr int HID_D  = 512;
constexpr int N_LAY  = 8;
constexpr int N_T    = 32;          // F/2
constexpr int IN_DIM = 160;         // N_T + CTX
constexpr int TB     = 32;          // samples per CTA
constexpr int NTHR   = 256;
}

// Generic [TB x K] @ [K x 512] + bias -> relu -> outbuf (SMEM, row stride 512).
// Thread layout: tx in [0,32) covers neurons {128u + 4tx + j}, ty in [0,8) covers
// samples srow..srow+3. Reads of `in` are warp-broadcast LDS; W loads are
// coalesced LDG.128. Safe for in == outbuf (compute-all, barrier, write, barrier).
template<int K>
__device__ __forceinline__ void dense_relu_512(
    const float* __restrict__ in, const int instride,
    const float* __restrict__ W,       // row-major [K][512]
    const float* __restrict__ bias,    // [512]
    float* __restrict__ outbuf,        // [TB][512]
    const int tx, const int srow)
{
    float acc[4][16];
#pragma unroll
    for (int u = 0; u < 4; ++u) {
        float4 b4 = *((const float4*)bias + tx + 32 * u);
#pragma unroll
        for (int si = 0; si < 4; ++si) {
            acc[si][4*u+0] = b4.x; acc[si][4*u+1] = b4.y;
            acc[si][4*u+2] = b4.z; acc[si][4*u+3] = b4.w;
        }
    }

    for (int k = 0; k < K; k += 4) {
        float4 av[4];
#pragma unroll
        for (int si = 0; si < 4; ++si)
            av[si] = *(const float4*)&in[(srow + si) * instride + k];
#pragma unroll
        for (int kk = 0; kk < 4; ++kk) {
#pragma unroll
            for (int u = 0; u < 4; ++u) {
                float4 w = *((const float4*)&W[(k + kk) * HID_D] + tx + 32 * u);
#pragma unroll
                for (int si = 0; si < 4; ++si) {
                    const float a = reinterpret_cast<const float*>(&av[si])[kk];
                    acc[si][4*u+0] = fmaf(a, w.x, acc[si][4*u+0]);
                    acc[si][4*u+1] = fmaf(a, w.y, acc[si][4*u+1]);
                    acc[si][4*u+2] = fmaf(a, w.z, acc[si][4*u+2]);
                    acc[si][4*u+3] = fmaf(a, w.w, acc[si][4*u+3]);
                }
            }
        }
    }

    __syncthreads();   // everyone done reading `in` before we overwrite it
#pragma unroll
    for (int si = 0; si < 4; ++si) {
#pragma unroll
        for (int u = 0; u < 4; ++u) {
            float4 r;
            r.x = fmaxf(acc[si][4*u+0], 0.0f);
            r.y = fmaxf(acc[si][4*u+1], 0.0f);
            r.z = fmaxf(acc[si][4*u+2], 0.0f);
            r.w = fmaxf(acc[si][4*u+3], 0.0f);
            *(float4*)&outbuf[(srow + si) * HID_D + 4 * tx + 128 * u] = r;
        }
    }
    __syncthreads();
}

__global__ __launch_bounds__(NTHR, 2)
void maf_fused_kernel(
    const float* __restrict__ inputs,   // [B,64]
    const float* __restrict__ context,  // [B,128]
    const float* __restrict__ W_in,     // [L,160,512]
    const float* __restrict__ b_in,     // [L,512]
    const float* __restrict__ W_h,      // [L,2,512,512]
    const float* __restrict__ b_h,      // [L,2,512]
    const float* __restrict__ W_out,    // [L,512,64]
    const float* __restrict__ b_out,    // [L,64]
    const int*   __restrict__ perms,    // [L-1,64]
    float* __restrict__ out)            // [B*64] x, then [B] logdet
{
    extern __shared__ float smem[];
    float* act   = smem;                       // TB*HID   (h buffer)
    float* actA  = act  + TB * HID_D;          // TB*IN_DIM (GEMM1 input)
    float* xbuf0 = actA + TB * IN_DIM;         // TB*F
    float* xbuf1 = xbuf0 + TB * F_DIM;         // TB*F
    int*   pm    = (int*)(xbuf1 + TB * F_DIM); // 64

    const int tid  = threadIdx.x;
    const int tx   = tid & 31;
    const int ty   = tid >> 5;
    const int srow = ty * 4;
    const int base = blockIdx.x * TB;

    // x = clip(inputs, -1, 1)
    for (int idx = tid; idx < TB * F_DIM; idx += NTHR) {
        float v = inputs[base * F_DIM + idx];
        xbuf0[idx] = fminf(1.0f, fmaxf(-1.0f, v));
    }
    // context staged ONCE into actA[:, 32:160] (never changes across layers)
    for (int idx = tid; idx < TB * CTX_D; idx += NTHR) {
        int s = idx >> 7, c = idx & 127;
        actA[s * IN_DIM + N_T + c] = context[(base + s) * CTX_D + c];
    }

    float ldacc[4] = {0.0f, 0.0f, 0.0f, 0.0f};
    float* xc = xbuf0;
    float* xn = xbuf1;
    __syncthreads();

    for (int layer = 0; layer < N_LAY; ++layer) {
        const int idOff = (layer & 1) ? 0 : 1;   // id_idx  = 2j + idOff
        const int tOff  = (layer & 1) ? 1 : 0;   // t_idx   = 2j + tOff

        if (layer < N_LAY - 1 && tid < F_DIM)
            pm[tid] = perms[layer * F_DIM + tid];

        // id_split -> actA[:, 0:32]
        for (int idx = tid; idx < TB * N_T; idx += NTHR) {
            int s = idx >> 5, j = idx & 31;
            actA[s * IN_DIM + j] = xc[s * F_DIM + 2 * j + idOff];
        }
        __syncthreads();

        // h = relu(a @ W_in + b_in)
        dense_relu_512<IN_DIM>(actA, IN_DIM,
                               W_in + layer * IN_DIM * HID_D,
                               b_in + layer * HID_D,
                               act, tx, srow);
        // two hidden blocks
        dense_relu_512<HID_D>(act, HID_D,
                              W_h + (layer * 2 + 0) * HID_D * HID_D,
                              b_h + (layer * 2 + 0) * HID_D,
                              act, tx, srow);
        dense_relu_512<HID_D>(act, HID_D,
                              W_h + (layer * 2 + 1) * HID_D * HID_D,
                              b_h + (layer * 2 + 1) * HID_D,
                              act, tx, srow);

        // p = h @ W_out + b_out  (N=64: lane tx owns shift[tx] and prescale[tx])
        {
            const float* W    = W_out + layer * HID_D * F_DIM;
            const float* bias = b_out + layer * F_DIM;
            float p0[4], p1[4];
            const float bs0 = bias[tx];
            const float bs1 = bias[tx + 32];
#pragma unroll
            for (int si = 0; si < 4; ++si) { p0[si] = bs0; p1[si] = bs1; }

            for (int k = 0; k < HID_D; k += 4) {
                float4 av[4];
#pragma unroll
                for (int si = 0; si < 4; ++si)
                    av[si] = *(const float4*)&act[(srow + si) * HID_D + k];
#pragma unroll
                for (int kk = 0; kk < 4; ++kk) {
                    const float w0 = W[(k + kk) * F_DIM + tx];
                    const float w1 = W[(k + kk) * F_DIM + tx + 32];
#pragma unroll
                    for (int si = 0; si < 4; ++si) {
                        const float a = reinterpret_cast<const float*>(&av[si])[kk];
                        p0[si] = fmaf(a, w0, p0[si]);
                        p1[si] = fmaf(a, w1, p1[si]);
                    }
                }
            }

            // epilogue: scale/shift the transform half, accumulate logdet
#pragma unroll
            for (int si = 0; si < 4; ++si) {
                const float sc = 1.0f / (1.0f + expf(-(p1[si] + 2.0f))) + 0.001f;
                const float sh = p0[si];
                const int   s  = srow + si;
                const int   f  = 2 * tx + tOff;
                const float tr = xc[s * F_DIM + f];
                xc[s * F_DIM + f] = fmaf(tr, sc, sh);
                float ls = logf(sc);
#pragma unroll
                for (int off = 16; off > 0; off >>= 1)
                    ls += __shfl_xor_sync(0xffffffffu, ls, off);
                ldacc[si] += ls;
            }
        }

        __syncthreads();  // t-feature updates visible to all

        if (layer < N_LAY - 1) {
            // x = x[:, perm]
            for (int idx = tid; idx < TB * F_DIM; idx += NTHR) {
                int s = idx >> 6, f = idx & 63;
                xn[idx] = xc[s * F_DIM + pm[f]];
            }
            float* t = xc; xc = xn; xn = t;
            __syncthreads();
        }
    }

    // output: clip(x) then logdet
    for (int idx = tid; idx < TB * F_DIM; idx += NTHR)
        out[base * F_DIM + idx] = fminf(1.0f, fmaxf(-1.0f, xc[idx]));

    if (tx == 0) {
#pragma unroll
        for (int si = 0; si < 4; ++si)
            out[B_TOT * F_DIM + base + srow + si] = ldacc[si];
    }
}

extern "C" void kernel_launch(void* const* d_in, const int* in_sizes, int n_in,
                              void* d_out, int out_size)
{
    const float* inputs  = (const float*)d_in[0];
    const float* context = (const float*)d_in[1];
    const float* W_in    = (const float*)d_in[2];
    const float* b_in    = (const float*)d_in[3];
    const float* W_h     = (const float*)d_in[4];
    const float* b_h     = (const float*)d_in[5];
    const float* W_out   = (const float*)d_in[6];
    const float* b_out   = (const float*)d_in[7];
    const int*   perms   = (const int*)d_in[8];
    float* out = (float*)d_out;

    const int smem_bytes = (TB * HID_D + TB * IN_DIM + 2 * TB * F_DIM + 64) * (int)sizeof(float);
    cudaFuncSetAttribute(maf_fused_kernel,
                         cudaFuncAttributeMaxDynamicSharedMemorySize, smem_bytes);

    dim3 grid(B_TOT / TB);
    dim3 block(NTHR);
    maf_fused_kernel<<<grid, block, smem_bytes>>>(
        inputs, context, W_in, b_in, W_h, b_h, W_out, b_out, perms, out);
}

// round 6
// speedup vs baseline: 1.0028x; 1.0026x over previous
#include <cuda_runtime.h>
#include <math.h>

// MaskedAutoregressiveFlow: fused 8-layer coupling flow.
// B=16384, F=64, CTX=128, HID=512, L=8, NB=2.
// One persistent-style fused kernel: 512 CTAs x 256 threads, 32 samples/CTA.
// All activations stay in SMEM; weights stream through L2.

namespace {
constexpr int B_TOT  = 16384;
constexpr int F_DIM  = 64;
constexpr int CTX_D  = 128;
constexpr int HID_D  = 512;
constexpr int N_LAY  = 8;
constexpr int N_T    = 32;          // F/2
constexpr int IN_DIM = 160;         // N_T + CTX
constexpr int TB     = 32;          // samples per CTA
constexpr int NTHR   = 256;
}

// Generic [TB x K] @ [K x 512] + bias -> relu -> outbuf (SMEM, row stride 512).
// Thread layout: tx in [0,32) covers neurons {128u + 4tx + j}, ty in [0,8) covers
// samples srow..srow+3. Reads of `in` are warp-broadcast LDS; W loads are
// coalesced LDG.128. Safe for in == outbuf (compute-all, barrier, write, barrier).
template<int K>
__device__ __forceinline__ void dense_relu_512(
    const float* __restrict__ in, const int instride,
    const float* __restrict__ W,       // row-major [K][512]
    const float* __restrict__ bias,    // [512]
    float* __restrict__ outbuf,        // [TB][512]
    const int tx, const int srow)
{
    float acc[4][16];
#pragma unroll
    for (int u = 0; u < 4; ++u) {
        float4 b4 = *((const float4*)bias + tx + 32 * u);
#pragma unroll
        for (int si = 0; si < 4; ++si) {
            acc[si][4*u+0] = b4.x; acc[si][4*u+1] = b4.y;
            acc[si][4*u+2] = b4.z; acc[si][4*u+3] = b4.w;
        }
    }

    for (int k = 0; k < K; k += 4) {
        float4 av[4];
#pragma unroll
        for (int si = 0; si < 4; ++si)
            av[si] = *(const float4*)&in[(srow + si) * instride + k];
#pragma unroll
        for (int kk = 0; kk < 4; ++kk) {
#pragma unroll
            for (int u = 0; u < 4; ++u) {
                float4 w = *((const float4*)&W[(k + kk) * HID_D] + tx + 32 * u);
#pragma unroll
                for (int si = 0; si < 4; ++si) {
                    const float a = reinterpret_cast<const float*>(&av[si])[kk];
                    acc[si][4*u+0] = fmaf(a, w.x, acc[si][4*u+0]);
                    acc[si][4*u+1] = fmaf(a, w.y, acc[si][4*u+1]);
                    acc[si][4*u+2] = fmaf(a, w.z, acc[si][4*u+2]);
                    acc[si][4*u+3] = fmaf(a, w.w, acc[si][4*u+3]);
                }
            }
        }
    }

    __syncthreads();   // everyone done reading `in` before we overwrite it
#pragma unroll
    for (int si = 0; si < 4; ++si) {
#pragma unroll
        for (int u = 0; u < 4; ++u) {
            float4 r;
            r.x = fmaxf(acc[si][4*u+0], 0.0f);
            r.y = fmaxf(acc[si][4*u+1], 0.0f);
            r.z = fmaxf(acc[si][4*u+2], 0.0f);
            r.w = fmaxf(acc[si][4*u+3], 0.0f);
            *(float4*)&outbuf[(srow + si) * HID_D + 4 * tx + 128 * u] = r;
        }
    }
    __syncthreads();
}

__global__ __launch_bounds__(NTHR, 2)
void maf_fused_kernel(
    const float* __restrict__ inputs,   // [B,64]
    const float* __restrict__ context,  // [B,128]
    const float* __restrict__ W_in,     // [L,160,512]
    const float* __restrict__ b_in,     // [L,512]
    const float* __restrict__ W_h,      // [L,2,512,512]
    const float* __restrict__ b_h,      // [L,2,512]
    const float* __restrict__ W_out,    // [L,512,64]
    const float* __restrict__ b_out,    // [L,64]
    const int*   __restrict__ perms,    // [L-1,64]
    float* __restrict__ out)            // [B*64] x, then [B] logdet
{
    extern __shared__ float smem[];
    float* act   = smem;                       // TB*HID   (h buffer)
    float* actA  = act  + TB * HID_D;          // TB*IN_DIM (GEMM1 input)
    float* xbuf0 = actA + TB * IN_DIM;         // TB*F
    float* xbuf1 = xbuf0 + TB * F_DIM;         // TB*F
    int*   pm    = (int*)(xbuf1 + TB * F_DIM); // 64

    const int tid  = threadIdx.x;
    const int tx   = tid & 31;
    const int ty   = tid >> 5;
    const int srow = ty * 4;
    const int base = blockIdx.x * TB;

    // x = clip(inputs, -1, 1)
    for (int idx = tid; idx < TB * F_DIM; idx += NTHR) {
        float v = inputs[base * F_DIM + idx];
        xbuf0[idx] = fminf(1.0f, fmaxf(-1.0f, v));
    }
    // context staged ONCE into actA[:, 32:160] (never changes across layers)
    for (int idx = tid; idx < TB * CTX_D; idx += NTHR) {
        int s = idx >> 7, c = idx & 127;
        actA[s * IN_DIM + N_T + c] = context[(base + s) * CTX_D + c];
    }

    float ldacc[4] = {0.0f, 0.0f, 0.0f, 0.0f};
    float* xc = xbuf0;
    float* xn = xbuf1;
    __syncthreads();

    for (int layer = 0; layer < N_LAY; ++layer) {
        const int idOff = (layer & 1) ? 0 : 1;   // id_idx  = 2j + idOff
        const int tOff  = (layer & 1) ? 1 : 0;   // t_idx   = 2j + tOff

        if (layer < N_LAY - 1 && tid < F_DIM)
            pm[tid] = perms[layer * F_DIM + tid];

        // id_split -> actA[:, 0:32]
        for (int idx = tid; idx < TB * N_T; idx += NTHR) {
            int s = idx >> 5, j = idx & 31;
            actA[s * IN_DIM + j] = xc[s * F_DIM + 2 * j + idOff];
        }
        __syncthreads();

        // h = relu(a @ W_in + b_in)
        dense_relu_512<IN_DIM>(actA, IN_DIM,
                               W_in + layer * IN_DIM * HID_D,
                               b_in + layer * HID_D,
                               act, tx, srow);
        // two hidden blocks
        dense_relu_512<HID_D>(act, HID_D,
                              W_h + (layer * 2 + 0) * HID_D * HID_D,
                              b_h + (layer * 2 + 0) * HID_D,
                              act, tx, srow);
        dense_relu_512<HID_D>(act, HID_D,
                              W_h + (layer * 2 + 1) * HID_D * HID_D,
                              b_h + (layer * 2 + 1) * HID_D,
                              act, tx, srow);

        // p = h @ W_out + b_out  (N=64: lane tx owns shift[tx] and prescale[tx])
        {
            const float* W    = W_out + layer * HID_D * F_DIM;
            const float* bias = b_out + layer * F_DIM;
            float p0[4], p1[4];
            const float bs0 = bias[tx];
            const float bs1 = bias[tx + 32];
#pragma unroll
            for (int si = 0; si < 4; ++si) { p0[si] = bs0; p1[si] = bs1; }

            for (int k = 0; k < HID_D; k += 4) {
                float4 av[4];
#pragma unroll
                for (int si = 0; si < 4; ++si)
                    av[si] = *(const float4*)&act[(srow + si) * HID_D + k];
#pragma unroll
                for (int kk = 0; kk < 4; ++kk) {
                    const float w0 = W[(k + kk) * F_DIM + tx];
                    const float w1 = W[(k + kk) * F_DIM + tx + 32];
#pragma unroll
                    for (int si = 0; si < 4; ++si) {
                        const float a = reinterpret_cast<const float*>(&av[si])[kk];
                        p0[si] = fmaf(a, w0, p0[si]);
                        p1[si] = fmaf(a, w1, p1[si]);
                    }
                }
            }

            // epilogue: scale/shift the transform half, accumulate logdet
#pragma unroll
            for (int si = 0; si < 4; ++si) {
                const float sc = 1.0f / (1.0f + expf(-(p1[si] + 2.0f))) + 0.001f;
                const float sh = p0[si];
                const int   s  = srow + si;
                const int   f  = 2 * tx + tOff;
                const float tr = xc[s * F_DIM + f];
                xc[s * F_DIM + f] = fmaf(tr, sc, sh);
                float ls = logf(sc);
#pragma unroll
                for (int off = 16; off > 0; off >>= 1)
                    ls += __shfl_xor_sync(0xffffffffu, ls, off);
                ldacc[si] += ls;
            }
        }

        __syncthreads();  // t-feature updates visible to all

        if (layer < N_LAY - 1) {
            // x = x[:, perm]
            for (int idx = tid; idx < TB * F_DIM; idx += NTHR) {
                int s = idx >> 6, f = idx & 63;
                xn[idx] = xc[s * F_DIM + pm[f]];
            }
            float* t = xc; xc = xn; xn = t;
            __syncthreads();
        }
    }

    // output: clip(x) then logdet
    for (int idx = tid; idx < TB * F_DIM; idx += NTHR)
        out[base * F_DIM + idx] = fminf(1.0f, fmaxf(-1.0f, xc[idx]));

    if (tx == 0) {
#pragma unroll
        for (int si = 0; si < 4; ++si)
            out[B_TOT * F_DIM + base + srow + si] = ldacc[si];
    }
}

extern "C" void kernel_launch(void* const* d_in, const int* in_sizes, int n_in,
                              void* d_out, int out_size)
{
    const float* inputs  = (const float*)d_in[0];
    const float* context = (const float*)d_in[1];
    const float* W_in    = (const float*)d_in[2];
    const float* b_in    = (const float*)d_in[3];
    const float* W_h     = (const float*)d_in[4];
    const float* b_h     = (const float*)d_in[5];
    const float* W_out   = (const float*)d_in[6];
    const float* b_out   = (const float*)d_in[7];
    const int*   perms   = (const int*)d_in[8];
    float* out = (float*)d_out;

    const int smem_bytes = (TB * HID_D + TB * IN_DIM + 2 * TB * F_DIM + 64) * (int)sizeof(float);
    cudaFuncSetAttribute(maf_fused_kernel,
                         cudaFuncAttributeMaxDynamicSharedMemorySize, smem_bytes);

    dim3 grid(B_TOT / TB);
    dim3 block(NTHR);
    maf_fused_kernel<<<grid, block, smem_bytes>>>(
        inputs, context, W_in, b_in, W_h, b_h, W_out, b_out, perms, out);
}